// round 1
// baseline (speedup 1.0000x reference)
#include <cuda_runtime.h>

// Row-major 3x4 top of the SE3 matrix: rows 0..2, 4 entries each (R | t).
// Bottom row is [0,0,0,1] => output row 3 == input row 3 (copy).
__device__ float g_M[12];

// One-thread prologue: build the SE3 exp matrix, and handle the scalar tail
// (n not divisible by 4) so the main kernel can be purely float4.
__global__ void se3_build_M_kernel(const float* __restrict__ w,
                                   const float* __restrict__ v,
                                   const float* __restrict__ theta,
                                   const float* __restrict__ x,
                                   float* __restrict__ y,
                                   long long n, long long n4)
{
    if (blockIdx.x != 0 || threadIdx.x != 0) return;

    const float wx = w[0], wy = w[1], wz = w[2];
    const float vx = v[0], vy = v[1], vz = v[2];
    const float th = theta[0];
    const float s = sinf(th);
    const float c = cosf(th);
    const float a = 1.0f - c;      // for R
    const float b = th - s;        // for V

    // K (skew-symmetric of w)
    float K[9] = { 0.0f, -wz,   wy,
                   wz,   0.0f, -wx,
                  -wy,   wx,   0.0f };
    // KK = K @ K
    float KK[9];
    #pragma unroll
    for (int r = 0; r < 3; ++r)
        #pragma unroll
        for (int col = 0; col < 3; ++col) {
            float acc = 0.0f;
            #pragma unroll
            for (int k = 0; k < 3; ++k)
                acc += K[r*3 + k] * K[k*3 + col];
            KK[r*3 + col] = acc;
        }

    float R[9], V[9];
    #pragma unroll
    for (int i = 0; i < 9; ++i) {
        const float I = (i == 0 || i == 4 || i == 8) ? 1.0f : 0.0f;
        R[i] = I + s * K[i] + a * KK[i];
        V[i] = I * th + a * K[i] + b * KK[i];
    }

    float t0 = V[0]*vx + V[1]*vy + V[2]*vz;
    float t1 = V[3]*vx + V[4]*vy + V[5]*vz;
    float t2 = V[6]*vx + V[7]*vy + V[8]*vz;

    g_M[0] = R[0]; g_M[1] = R[1]; g_M[2]  = R[2]; g_M[3]  = t0;
    g_M[4] = R[3]; g_M[5] = R[4]; g_M[6]  = R[5]; g_M[7]  = t1;
    g_M[8] = R[6]; g_M[9] = R[7]; g_M[10] = R[8]; g_M[11] = t2;

    // Scalar tail: columns [4*n4, n)
    for (long long j = 4*n4; j < n; ++j) {
        const float x0 = x[0*n + j];
        const float x1 = x[1*n + j];
        const float x2 = x[2*n + j];
        const float x3 = x[3*n + j];
        y[0*n + j] = R[0]*x0 + R[1]*x1 + R[2]*x2 + t0*x3;
        y[1*n + j] = R[3]*x0 + R[4]*x1 + R[5]*x2 + t1*x3;
        y[2*n + j] = R[6]*x0 + R[7]*x1 + R[8]*x2 + t2*x3;
        y[3*n + j] = x3;
    }
}

__global__ __launch_bounds__(256)
void se3_apply_kernel(const float4* __restrict__ x,
                      float4* __restrict__ y,
                      long long n4)
{
    const long long i = (long long)blockIdx.x * blockDim.x + threadIdx.x;
    if (i >= n4) return;

    // 12 uniform loads, broadcast + cached
    const float m00 = g_M[0], m01 = g_M[1], m02 = g_M[2],  m03 = g_M[3];
    const float m10 = g_M[4], m11 = g_M[5], m12 = g_M[6],  m13 = g_M[7];
    const float m20 = g_M[8], m21 = g_M[9], m22 = g_M[10], m23 = g_M[11];

    // 4 independent 128-bit loads (MLP=4)
    const float4 r0 = x[i];
    const float4 r1 = x[i + n4];
    const float4 r2 = x[i + 2*n4];
    const float4 r3 = x[i + 3*n4];

    float4 o0, o1, o2;
    o0.x = m00*r0.x + m01*r1.x + m02*r2.x + m03*r3.x;
    o0.y = m00*r0.y + m01*r1.y + m02*r2.y + m03*r3.y;
    o0.z = m00*r0.z + m01*r1.z + m02*r2.z + m03*r3.z;
    o0.w = m00*r0.w + m01*r1.w + m02*r2.w + m03*r3.w;

    o1.x = m10*r0.x + m11*r1.x + m12*r2.x + m13*r3.x;
    o1.y = m10*r0.y + m11*r1.y + m12*r2.y + m13*r3.y;
    o1.z = m10*r0.z + m11*r1.z + m12*r2.z + m13*r3.z;
    o1.w = m10*r0.w + m11*r1.w + m12*r2.w + m13*r3.w;

    o2.x = m20*r0.x + m21*r1.x + m22*r2.x + m23*r3.x;
    o2.y = m20*r0.y + m21*r1.y + m22*r2.y + m23*r3.y;
    o2.z = m20*r0.z + m21*r1.z + m22*r2.z + m23*r3.z;
    o2.w = m20*r0.w + m21*r1.w + m22*r2.w + m23*r3.w;

    y[i]        = o0;
    y[i + n4]   = o1;
    y[i + 2*n4] = o2;
    y[i + 3*n4] = r3;   // bottom row of M is [0,0,0,1]
}

extern "C" void kernel_launch(void* const* d_in, const int* in_sizes, int n_in,
                              void* d_out, int out_size)
{
    const float* x     = (const float*)d_in[0];   // [4, N]
    const float* w     = (const float*)d_in[1];   // [3]
    const float* v     = (const float*)d_in[2];   // [3]
    const float* theta = (const float*)d_in[3];   // []
    float* y = (float*)d_out;                     // [4, N]

    const long long n  = (long long)in_sizes[0] / 4;  // N columns
    const long long n4 = n / 4;                       // float4 chunks per row

    se3_build_M_kernel<<<1, 32>>>(w, v, theta, x, y, n, n4);

    const int threads = 256;
    const long long blocks = (n4 + threads - 1) / threads;
    se3_apply_kernel<<<(unsigned int)blocks, threads>>>(
        (const float4*)x, (float4*)y, n4);
}

// round 2
// speedup vs baseline: 1.0297x; 1.0297x over previous
#include <cuda_runtime.h>

// Fully fused: every thread redundantly builds the 3x4 SE3 matrix from the 7
// input scalars (broadcast loads, ~50 FMAs + sincos — free under memory-bound
// issue slack), then streams its float4 column block. Bottom row of M is
// [0,0,0,1] so output row 3 is a copy of input row 3.
__global__ __launch_bounds__(256)
void se3_fused_kernel(const float4* __restrict__ x,
                      float4* __restrict__ y,
                      const float* __restrict__ w,
                      const float* __restrict__ v,
                      const float* __restrict__ theta,
                      long long n, long long n4)
{
    const long long i = (long long)blockIdx.x * blockDim.x + threadIdx.x;

    // ---- Build M (rows 0..2 of the SE3 exp) ----
    const float wx = __ldg(&w[0]), wy = __ldg(&w[1]), wz = __ldg(&w[2]);
    const float vx = __ldg(&v[0]), vy = __ldg(&v[1]), vz = __ldg(&v[2]);
    const float th = __ldg(&theta[0]);
    float s, c;
    __sincosf(th, &s, &c);
    // __sincosf is the fast-math approx; theta ~1e-6 so it's exact to ulp here,
    // but use precise versions to be safe vs. the 1e-3 rel-err gate on any seed:
    s = sinf(th); c = cosf(th);
    const float a = 1.0f - c;   // R coefficient
    const float b = th - s;     // V coefficient

    const float K[9] = { 0.0f, -wz,   wy,
                         wz,   0.0f, -wx,
                        -wy,   wx,   0.0f };
    float KK[9];
    #pragma unroll
    for (int r = 0; r < 3; ++r)
        #pragma unroll
        for (int col = 0; col < 3; ++col)
            KK[r*3+col] = K[r*3+0]*K[0*3+col] + K[r*3+1]*K[1*3+col] + K[r*3+2]*K[2*3+col];

    float R[9], V[9];
    #pragma unroll
    for (int k = 0; k < 9; ++k) {
        const float I = (k == 0 || k == 4 || k == 8) ? 1.0f : 0.0f;
        R[k] = I + s * K[k] + a * KK[k];
        V[k] = I * th + a * K[k] + b * KK[k];
    }
    const float t0 = V[0]*vx + V[1]*vy + V[2]*vz;
    const float t1 = V[3]*vx + V[4]*vy + V[5]*vz;
    const float t2 = V[6]*vx + V[7]*vy + V[8]*vz;

    // ---- Streaming transform ----
    if (i < n4) {
        const float4 r0 = __ldcs(&x[i]);
        const float4 r1 = __ldcs(&x[i + n4]);
        const float4 r2 = __ldcs(&x[i + 2*n4]);
        const float4 r3 = __ldcs(&x[i + 3*n4]);

        float4 o0, o1, o2;
        o0.x = R[0]*r0.x + R[1]*r1.x + R[2]*r2.x + t0*r3.x;
        o0.y = R[0]*r0.y + R[1]*r1.y + R[2]*r2.y + t0*r3.y;
        o0.z = R[0]*r0.z + R[1]*r1.z + R[2]*r2.z + t0*r3.z;
        o0.w = R[0]*r0.w + R[1]*r1.w + R[2]*r2.w + t0*r3.w;

        o1.x = R[3]*r0.x + R[4]*r1.x + R[5]*r2.x + t1*r3.x;
        o1.y = R[3]*r0.y + R[4]*r1.y + R[5]*r2.y + t1*r3.y;
        o1.z = R[3]*r0.z + R[4]*r1.z + R[5]*r2.z + t1*r3.z;
        o1.w = R[3]*r0.w + R[4]*r1.w + R[5]*r2.w + t1*r3.w;

        o2.x = R[6]*r0.x + R[7]*r1.x + R[8]*r2.x + t2*r3.x;
        o2.y = R[6]*r0.y + R[7]*r1.y + R[8]*r2.y + t2*r3.y;
        o2.z = R[6]*r0.z + R[7]*r1.z + R[8]*r2.z + t2*r3.z;
        o2.w = R[6]*r0.w + R[7]*r1.w + R[8]*r2.w + t2*r3.w;

        __stcs(&y[i],        o0);
        __stcs(&y[i + n4],   o1);
        __stcs(&y[i + 2*n4], o2);
        __stcs(&y[i + 3*n4], r3);   // bottom row = [0,0,0,1]
    }

    // ---- Scalar tail (n not divisible by 4) ----
    const long long tail = n - 4*n4;
    if (i < tail) {
        const float* xf = (const float*)x;
        float* yf = (float*)y;
        const long long j = 4*n4 + i;
        const float x0 = xf[0*n + j];
        const float x1 = xf[1*n + j];
        const float x2 = xf[2*n + j];
        const float x3 = xf[3*n + j];
        yf[0*n + j] = R[0]*x0 + R[1]*x1 + R[2]*x2 + t0*x3;
        yf[1*n + j] = R[3]*x0 + R[4]*x1 + R[5]*x2 + t1*x3;
        yf[2*n + j] = R[6]*x0 + R[7]*x1 + R[8]*x2 + t2*x3;
        yf[3*n + j] = x3;
    }
}

extern "C" void kernel_launch(void* const* d_in, const int* in_sizes, int n_in,
                              void* d_out, int out_size)
{
    const float* x     = (const float*)d_in[0];   // [4, N]
    const float* w     = (const float*)d_in[1];   // [3]
    const float* v     = (const float*)d_in[2];   // [3]
    const float* theta = (const float*)d_in[3];   // []
    float* y = (float*)d_out;                     // [4, N]

    const long long n  = (long long)in_sizes[0] / 4;  // N columns
    const long long n4 = n / 4;                       // float4 chunks per row

    const int threads = 256;
    const long long blocks = (n4 + threads - 1) / threads;  // covers tail too (tail < 4 <= n4 range)
    se3_fused_kernel<<<(unsigned int)blocks, threads>>>(
        (const float4*)x, (float4*)y, w, v, theta, n, n4);
}